// round 3
// baseline (speedup 1.0000x reference)
#include <cuda_runtime.h>

#define H 448
#define CIN 64
#define COUT 64
#define NB 32      // 14x14 output blocks per spatial dim (448/14)
#define BS 14      // block stride / output block size
#define GW 16      // gather window (with 1px halo)
#define CCH 8      // cin chunk staged through smem

// active flags for up to N=4 batches of 32x32 blocks
__device__ unsigned char g_active[4 * NB * NB];

// Kernel 1: block activity = max over 16x16 window at offset -1, stride 14 (OOB skipped)
__global__ void sbnet_mask_kernel(const float* __restrict__ mask, int n_total) {
    int idx = blockIdx.x * blockDim.x + threadIdx.x;
    if (idx >= n_total) return;
    int bx = idx % NB;
    int by = (idx / NB) % NB;
    int n  = idx / (NB * NB);
    int r0 = by * BS - 1, c0 = bx * BS - 1;
    float m = -1e30f;
    for (int r = 0; r < GW; ++r) {
        int rr = r0 + r;
        if (rr < 0 || rr >= H) continue;
        const float* mrow = mask + ((long)n * H + rr) * H;
        int clo = (c0 < 0) ? 1 : 0;
        int chi = (c0 + GW > H) ? (GW - 1) : GW;
        for (int c = clo; c < chi; ++c) {
            m = fmaxf(m, mrow[c0 + c]);
        }
    }
    g_active[idx] = (m > 0.5f) ? 1 : 0;
}

// Kernel 2: per-block direct conv. CTA = (n, by, bx). 224 threads:
//   cg  = tid / 14  (16 groups of 4 couts)
//   row = tid % 14  (output row in block)
// Each thread accumulates 4 couts x 14 cols in registers.
__global__ void __launch_bounds__(224, 2)
sbnet_conv_kernel(const float* __restrict__ x, const float* __restrict__ w,
                  const float* __restrict__ bias, float* __restrict__ out) {
    __shared__ float s_in[CCH][GW][GW + 1];   // +1 pad -> conflict-free row reads
    __shared__ float s_w[CCH][COUT][9];

    const int tid = threadIdx.x;
    const int bx = blockIdx.x % NB;
    const int by = blockIdx.x / NB;
    const int n  = blockIdx.y;
    const int cg  = tid / BS;   // 0..15
    const int row = tid % BS;   // 0..13
    const int gy = by * BS + row;
    const int gx0 = bx * BS;

    if (!g_active[n * NB * NB + blockIdx.x]) {
        // inactive block: write zeros (output is poisoned by harness)
        #pragma unroll
        for (int j = 0; j < 4; ++j) {
            float* orow = out + (((long)n * COUT + cg * 4 + j) * H + gy) * H + gx0;
            #pragma unroll
            for (int c = 0; c < BS; ++c) orow[c] = 0.0f;
        }
        return;
    }

    const int r0 = by * BS - 1, c0 = bx * BS - 1;

    float acc[4][BS];
    #pragma unroll
    for (int j = 0; j < 4; ++j) {
        float b = __ldg(&bias[cg * 4 + j]);
        #pragma unroll
        for (int c = 0; c < BS; ++c) acc[j][c] = b;
    }

    for (int ch = 0; ch < CIN / CCH; ++ch) {
        __syncthreads();
        // stage input halo tile: CCH x 16 x 16, zero-padded at borders
        for (int i = tid; i < CCH * GW * GW; i += 224) {
            int ci  = i >> 8;          // /256
            int rem = i & 255;
            int y   = rem >> 4;
            int xx  = rem & 15;
            int rr = r0 + y, cc2 = c0 + xx;
            float v = 0.0f;
            if (rr >= 0 && rr < H && cc2 >= 0 && cc2 < H)
                v = x[(((long)n * CIN + ch * CCH + ci) * H + rr) * H + cc2];
            s_in[ci][y][xx] = v;
        }
        // stage weights: s_w[ci][cout][9] from global w[cout][cin][3][3]
        for (int i = tid; i < CCH * COUT * 9; i += 224) {
            int ci  = i / (COUT * 9);
            int rem = i % (COUT * 9);
            int co  = rem / 9;
            int k   = rem % 9;
            s_w[ci][co][k] = w[((long)co * CIN + ch * CCH + ci) * 9 + k];
        }
        __syncthreads();

        #pragma unroll
        for (int ci = 0; ci < CCH; ++ci) {
            float wr[36];
            const float* wp = &s_w[ci][cg * 4][0];  // 36 contiguous floats (4 couts x 9)
            #pragma unroll
            for (int t = 0; t < 36; ++t) wr[t] = wp[t];

            #pragma unroll
            for (int dy = 0; dy < 3; ++dy) {
                float irow[GW];
                #pragma unroll
                for (int xx = 0; xx < GW; ++xx) irow[xx] = s_in[ci][row + dy][xx];
                #pragma unroll
                for (int j = 0; j < 4; ++j) {
                    #pragma unroll
                    for (int dx = 0; dx < 3; ++dx) {
                        float wv = wr[j * 9 + dy * 3 + dx];
                        #pragma unroll
                        for (int col = 0; col < BS; ++col)
                            acc[j][col] += wv * irow[col + dx];
                    }
                }
            }
        }
    }

    #pragma unroll
    for (int j = 0; j < 4; ++j) {
        float* orow = out + (((long)n * COUT + cg * 4 + j) * H + gy) * H + gx0;
        #pragma unroll
        for (int c = 0; c < BS; ++c) orow[c] = acc[j][c];
    }
}

extern "C" void kernel_launch(void* const* d_in, const int* in_sizes, int n_in,
                              void* d_out, int out_size) {
    const float* x    = (const float*)d_in[0];
    const float* mask = (const float*)d_in[1];
    const float* w    = (const float*)d_in[2];
    const float* bias = (const float*)d_in[3];
    float* out = (float*)d_out;

    int N = in_sizes[0] / (CIN * H * H);   // 4
    int nblk = N * NB * NB;                // 4096

    sbnet_mask_kernel<<<(nblk + 255) / 256, 256>>>(mask, nblk);
    sbnet_conv_kernel<<<dim3(NB * NB, (unsigned)N), 224>>>(x, w, bias, out);
}

// round 5
// speedup vs baseline: 1.8229x; 1.8229x over previous
#include <cuda_runtime.h>
#include <cuda_bf16.h>
#include <cstdint>

#define H    448
#define HH   (448*448)
#define CIN  64
#define COUT 64
#define NB   32
#define BS   14
#define HAL  18
#define NTHR 256

// ---- dynamic smem layout (bytes) ----
#define OFF_HALO_HI 0
#define HALO_BYTES  (HAL*HAL*128)            // 41472 (18x18 pixels x 128B)
#define OFF_HALO_LO 41472
#define OFF_WBUF    82944                    // 2 x 16384 (hi 8K + lo 8K each)
#define OFF_RAW     115712                   // 16 x 18 x 19 f32 = 21888
#define OFF_BIAS    137600                   // 64 f32
#define SMEM_TOTAL  137856

#define RAW19   19
#define RAWCIN  (HAL*RAW19)                  // 342 floats per cin

__device__ unsigned char g_active[4 * NB * NB];
// pre-swizzled per-tap weight images: [tap][hi 8192B][lo 8192B]
__device__ __align__(16) unsigned char g_wprep[9 * 16384];

// ---------------- helpers ----------------
__device__ __forceinline__ uint32_t smem_u32(const void* p) {
    uint32_t a;
    asm("{ .reg .u64 t; cvta.to.shared.u64 t, %1; cvt.u32.u64 %0, t; }" : "=r"(a) : "l"(p));
    return a;
}
__device__ __forceinline__ void ldsm_x4(uint32_t* r, uint32_t addr) {
    asm volatile("ldmatrix.sync.aligned.m8n8.x4.shared.b16 {%0,%1,%2,%3}, [%4];"
        : "=r"(r[0]), "=r"(r[1]), "=r"(r[2]), "=r"(r[3]) : "r"(addr));
}
__device__ __forceinline__ void ldsm_x2(uint32_t* r, uint32_t addr) {
    asm volatile("ldmatrix.sync.aligned.m8n8.x2.shared.b16 {%0,%1}, [%2];"
        : "=r"(r[0]), "=r"(r[1]) : "r"(addr));
}
__device__ __forceinline__ void mma16816(float* d, const uint32_t* a, const uint32_t* b) {
    asm volatile("mma.sync.aligned.m16n8k16.row.col.f32.bf16.bf16.f32 "
        "{%0,%1,%2,%3}, {%4,%5,%6,%7}, {%8,%9}, {%0,%1,%2,%3};"
        : "+f"(d[0]), "+f"(d[1]), "+f"(d[2]), "+f"(d[3])
        : "r"(a[0]), "r"(a[1]), "r"(a[2]), "r"(a[3]), "r"(b[0]), "r"(b[1]));
}
__device__ __forceinline__ uint32_t pack2(__nv_bfloat16 lo16, __nv_bfloat16 hi16) {
    return ((uint32_t)__bfloat16_as_ushort(hi16) << 16) | __bfloat16_as_ushort(lo16);
}

// ---------------- Kernel 0: weight prep (bf16 hi/lo, pre-swizzled images) ----------------
__global__ void sbnet_wprep_kernel(const float* __restrict__ w) {
    int i = blockIdx.x * 256 + threadIdx.x;
    if (i >= 9 * COUT * CIN) return;
    int tap = i >> 12;                 // /4096
    int rem = i & 4095;
    int co = rem >> 6, ci = rem & 63;
    float v = w[(co * CIN + ci) * 9 + tap];
    __nv_bfloat16 hv = __float2bfloat16(v);
    __nv_bfloat16 lv = __float2bfloat16(v - __bfloat162float(hv));
    int off = tap * 16384 + co * 128 + ((((ci >> 3) ^ (co & 7))) << 4) + (ci & 7) * 2;
    *(__nv_bfloat16*)(g_wprep + off) = hv;
    *(__nv_bfloat16*)(g_wprep + off + 8192) = lv;
}

// ---------------- Kernel 1: block activity ----------------
__global__ void sbnet_mask_kernel(const float* __restrict__ mask, int n_total) {
    int idx = blockIdx.x * blockDim.x + threadIdx.x;
    if (idx >= n_total) return;
    int bx = idx % NB;
    int by = (idx / NB) % NB;
    int n  = idx / (NB * NB);
    int r0 = by * BS - 1, c0 = bx * BS - 1;
    float m = -1e30f;
    for (int r = 0; r < 16; ++r) {
        int rr = r0 + r;
        if (rr < 0 || rr >= H) continue;
        const float* mrow = mask + ((long)n * H + rr) * H;
        int clo = (c0 < 0) ? 1 : 0;
        int chi = (c0 + 16 > H) ? 15 : 16;
        for (int c = clo; c < chi; ++c) m = fmaxf(m, mrow[c0 + c]);
    }
    g_active[idx] = (m > 0.5f) ? 1 : 0;
}

// ---------------- Kernel 2: HMMA block conv ----------------
__global__ void __launch_bounds__(NTHR)
sbnet_mma_kernel(const float* __restrict__ x, const float* __restrict__ bias,
                 float* __restrict__ out) {
    extern __shared__ char smem[];
    const int tid  = threadIdx.x;
    const int wid  = tid >> 5;
    const int lane = tid & 31;
    const int bx = blockIdx.x % NB;
    const int by = blockIdx.x / NB;
    const int n  = blockIdx.y;

    if (!g_active[n * NB * NB + blockIdx.x]) {
        for (int i = tid; i < COUT * BS * BS; i += NTHR) {
            int co = i / (BS * BS);
            int rem = i % (BS * BS);
            int y = rem / BS, xx = rem % BS;
            out[((size_t)(n * COUT + co)) * HH + (size_t)(by * BS + y) * H + bx * BS + xx] = 0.0f;
        }
        return;
    }

    const uint32_t smem_base = smem_u32(smem);
    float* s_bias = (float*)(smem + OFF_BIAS);
    if (tid < COUT) s_bias[tid] = bias[tid];

    // ---- build transposed bf16 hi/lo halo via fp32 scratch, 4 chunks of 16 cin ----
    const int r0 = by * BS - 1, c0 = bx * BS - 1;
    float* raw = (float*)(smem + OFF_RAW);
    for (int chunk = 0; chunk < 4; ++chunk) {
        __syncthreads();   // raw free (prev chunk consumed)
        for (int i = tid; i < 16 * HAL * HAL; i += NTHR) {
            int ci = i / (HAL * HAL);
            int rem = i % (HAL * HAL);
            int y = rem / HAL, xx = rem % HAL;
            int rr = r0 + y, cc = c0 + xx;
            float v = 0.0f;
            if (rr >= 0 && rr < H && cc >= 0 && cc < H)
                v = x[((size_t)(n * CIN + chunk * 16 + ci)) * HH + (size_t)rr * H + cc];
            raw[ci * RAWCIN + y * RAW19 + xx] = v;
        }
        __syncthreads();
        for (int pos = tid; pos < HAL * HAL; pos += NTHR) {
            int y = pos / HAL, xx = pos % HAL;
            uint32_t hu[8], lu[8];
            #pragma unroll
            for (int k = 0; k < 8; ++k) {
                float v0 = raw[(2 * k) * RAWCIN + y * RAW19 + xx];
                float v1 = raw[(2 * k + 1) * RAWCIN + y * RAW19 + xx];
                __nv_bfloat16 h0 = __float2bfloat16(v0);
                __nv_bfloat16 h1 = __float2bfloat16(v1);
                __nv_bfloat16 l0 = __float2bfloat16(v0 - __bfloat162float(h0));
                __nv_bfloat16 l1 = __float2bfloat16(v1 - __bfloat162float(h1));
                hu[k] = pack2(h0, h1);
                lu[k] = pack2(l0, l1);
            }
            int u0 = chunk * 2;
            int o0 = pos * 128 + (((u0    ) ^ (pos & 7)) << 4);
            int o1 = pos * 128 + (((u0 + 1) ^ (pos & 7)) << 4);
            *(uint4*)(smem + OFF_HALO_HI + o0) = make_uint4(hu[0], hu[1], hu[2], hu[3]);
            *(uint4*)(smem + OFF_HALO_HI + o1) = make_uint4(hu[4], hu[5], hu[6], hu[7]);
            *(uint4*)(smem + OFF_HALO_LO + o0) = make_uint4(lu[0], lu[1], lu[2], lu[3]);
            *(uint4*)(smem + OFF_HALO_LO + o1) = make_uint4(lu[4], lu[5], lu[6], lu[7]);
        }
    }

    // stage W tap 0 into buffer 0
    {
        const uint4* src = (const uint4*)(g_wprep);
        uint4* dst = (uint4*)(smem + OFF_WBUF);
        #pragma unroll
        for (int j = 0; j < 4; ++j) dst[tid + j * 256] = src[tid + j * 256];
    }
    __syncthreads();

    // ---- main loop over 9 taps ----
    const int mg = wid >> 1;          // m-group 0..3  (4 m16 tiles each)
    const int ng = wid & 1;           // n-group 0..1  (4 n8 tiles each)
    const int cA = lane & 15;         // A row (pixel x within y-row)
    const int ksubA = lane >> 4;      // A 16B half
    const int rB = lane & 7;          // B cout row within tile
    const int msB = (lane >> 3) & 1;  // B 16B half

    float acc[4][4][4];
    #pragma unroll
    for (int mt = 0; mt < 4; ++mt)
        #pragma unroll
        for (int nt = 0; nt < 4; ++nt)
            #pragma unroll
            for (int q = 0; q < 4; ++q) acc[mt][nt][q] = 0.0f;

    const uint32_t haloHi = smem_base + OFF_HALO_HI;
    const uint32_t haloLo = smem_base + OFF_HALO_LO;

    uint32_t coB[4];
    #pragma unroll
    for (int nt = 0; nt < 4; ++nt) coB[nt] = ng * 32 + nt * 8 + rB;

    #pragma unroll 1
    for (int tap = 0; tap < 9; ++tap) {
        const int dy = tap / 3, dx = tap - dy * 3;

        // prefetch next tap's W image
        uint4 wpre[4];
        const bool pre = (tap + 1 < 9);
        if (pre) {
            const uint4* src = (const uint4*)(g_wprep + (tap + 1) * 16384);
            #pragma unroll
            for (int j = 0; j < 4; ++j) wpre[j] = src[tid + j * 256];
        }

        uint32_t posm[4];
        #pragma unroll
        for (int mt = 0; mt < 4; ++mt)
            posm[mt] = (mg * 4 + mt + dy) * HAL + cA + dx;

        const uint32_t wb = smem_base + OFF_WBUF + (tap & 1) * 16384;

        #pragma unroll
        for (int ks = 0; ks < 4; ++ks) {
            uint32_t ah[4][4], al[4][4], bh[4][2], bl[4][2];
            #pragma unroll
            for (int mt = 0; mt < 4; ++mt) {
                if (mg * 4 + mt < 14) {
                    uint32_t off = posm[mt] * 128 +
                        (((uint32_t)(ks * 2 + ksubA) ^ (posm[mt] & 7)) << 4);
                    ldsm_x4(ah[mt], haloHi + off);
                    ldsm_x4(al[mt], haloLo + off);
                }
            }
            #pragma unroll
            for (int nt = 0; nt < 4; ++nt) {
                uint32_t off = coB[nt] * 128 +
                    (((uint32_t)(ks * 2 + msB) ^ (coB[nt] & 7)) << 4);
                ldsm_x2(bh[nt], wb + off);
                ldsm_x2(bl[nt], wb + 8192 + off);
            }
            #pragma unroll
            for (int mt = 0; mt < 4; ++mt) {
                if (mg * 4 + mt < 14) {
                    #pragma unroll
                    for (int nt = 0; nt < 4; ++nt) {
                        mma16816(acc[mt][nt], ah[mt], bh[nt]);
                        mma16816(acc[mt][nt], al[mt], bh[nt]);
                        mma16816(acc[mt][nt], ah[mt], bl[nt]);
                    }
                }
            }
        }

        if (pre) {
            uint4* dst = (uint4*)(smem + OFF_WBUF + ((tap + 1) & 1) * 16384);
            #pragma unroll
            for (int j = 0; j < 4; ++j) dst[tid + j * 256] = wpre[j];
        }
        __syncthreads();
    }

    // ---- epilogue: accums -> smem (aliases dead halo) -> coalesced gmem ----
    float* epi = (float*)smem;     // [224][66]
    const int g  = lane >> 2;
    const int tg = lane & 3;
    #pragma unroll
    for (int mt = 0; mt < 4; ++mt) {
        int tile = mg * 4 + mt;
        if (tile < 14) {
            #pragma unroll
            for (int nt = 0; nt < 4; ++nt) {
                int p  = tile * 16 + g;
                int co = ng * 32 + nt * 8 + 2 * tg;
                *(float2*)&epi[p * 66 + co]       = make_float2(acc[mt][nt][0], acc[mt][nt][1]);
                *(float2*)&epi[(p + 8) * 66 + co] = make_float2(acc[mt][nt][2], acc[mt][nt][3]);
            }
        }
    }
    __syncthreads();

    for (int i = tid; i < COUT * BS * BS; i += NTHR) {
        int co = i / (BS * BS);
        int rem = i % (BS * BS);
        int y = rem / BS, xx = rem % BS;
        float val = epi[(y * 16 + xx) * 66 + co] + s_bias[co];
        out[((size_t)(n * COUT + co)) * HH + (size_t)(by * BS + y) * H + bx * BS + xx] = val;
    }
}

extern "C" void kernel_launch(void* const* d_in, const int* in_sizes, int n_in,
                              void* d_out, int out_size) {
    const float* x    = (const float*)d_in[0];
    const float* mask = (const float*)d_in[1];
    const float* w    = (const float*)d_in[2];
    const float* bias = (const float*)d_in[3];
    float* out = (float*)d_out;

    int N = in_sizes[0] / (CIN * H * H);   // 4
    int nblk = N * NB * NB;

    cudaFuncSetAttribute(sbnet_mma_kernel,
                         cudaFuncAttributeMaxDynamicSharedMemorySize, SMEM_TOTAL);

    sbnet_wprep_kernel<<<(9 * COUT * CIN + 255) / 256, 256>>>(w);
    sbnet_mask_kernel<<<(nblk + 255) / 256, 256>>>(mask, nblk);
    sbnet_mma_kernel<<<dim3(NB * NB, (unsigned)N), NTHR, SMEM_TOTAL>>>(x, bias, out);
}

// round 6
// speedup vs baseline: 3.0466x; 1.6713x over previous
#include <cuda_runtime.h>
#include <cuda_fp16.h>
#include <cstdint>

#define H    448
#define HH   (448*448)
#define CIN  64
#define COUT 64
#define NB   32
#define BS   14
#define HAL  18
#define NTHR 256

// ---- dynamic smem layout (bytes) ----
#define OFF_HALO    0                        // 18x18 pixels x 128B fp16 = 41472
#define OFF_WBUF    41472                    // 2 x 16384 (hi 8K + lo 8K each)
#define OFF_RAW     41472                    // aliases WBUF during halo build (needs 21888)
#define OFF_BIAS    74240                    // 64 f32
#define SMEM_TOTAL  74496

#define RAW19   19
#define RAWCIN  (HAL*RAW19)                  // 342 floats per cin

__device__ unsigned char g_active[4 * NB * NB];
// pre-swizzled per-tap weight images: [tap][hi 8192B][lo 8192B]
__device__ __align__(16) unsigned char g_wprep[9 * 16384];

// ---------------- helpers ----------------
__device__ __forceinline__ uint32_t smem_u32(const void* p) {
    uint32_t a;
    asm("{ .reg .u64 t; cvta.to.shared.u64 t, %1; cvt.u32.u64 %0, t; }" : "=r"(a) : "l"(p));
    return a;
}
__device__ __forceinline__ void ldsm_x4(uint32_t* r, uint32_t addr) {
    asm volatile("ldmatrix.sync.aligned.m8n8.x4.shared.b16 {%0,%1,%2,%3}, [%4];"
        : "=r"(r[0]), "=r"(r[1]), "=r"(r[2]), "=r"(r[3]) : "r"(addr));
}
__device__ __forceinline__ void ldsm_x2(uint32_t* r, uint32_t addr) {
    asm volatile("ldmatrix.sync.aligned.m8n8.x2.shared.b16 {%0,%1}, [%2];"
        : "=r"(r[0]), "=r"(r[1]) : "r"(addr));
}
__device__ __forceinline__ void mma16816(float* d, const uint32_t* a, const uint32_t* b) {
    asm volatile("mma.sync.aligned.m16n8k16.row.col.f32.f16.f16.f32 "
        "{%0,%1,%2,%3}, {%4,%5,%6,%7}, {%8,%9}, {%0,%1,%2,%3};"
        : "+f"(d[0]), "+f"(d[1]), "+f"(d[2]), "+f"(d[3])
        : "r"(a[0]), "r"(a[1]), "r"(a[2]), "r"(a[3]), "r"(b[0]), "r"(b[1]));
}
__device__ __forceinline__ uint32_t pack2(__half a, __half b) {
    return ((uint32_t)__half_as_ushort(b) << 16) | __half_as_ushort(a);
}

// ---------------- Kernel 0: weight prep (fp16 hi/lo, pre-swizzled images) ----------------
__global__ void sbnet_wprep_kernel(const float* __restrict__ w) {
    int i = blockIdx.x * 256 + threadIdx.x;
    if (i >= 9 * COUT * CIN) return;
    int tap = i >> 12;
    int rem = i & 4095;
    int co = rem >> 6, ci = rem & 63;
    float v = w[(co * CIN + ci) * 9 + tap];
    __half hv = __float2half(v);
    __half lv = __float2half(v - __half2float(hv));
    int off = tap * 16384 + co * 128 + ((((ci >> 3) ^ (co & 7))) << 4) + (ci & 7) * 2;
    *(__half*)(g_wprep + off) = hv;
    *(__half*)(g_wprep + off + 8192) = lv;
}

// ---------------- Kernel 1: block activity ----------------
__global__ void sbnet_mask_kernel(const float* __restrict__ mask, int n_total) {
    int idx = blockIdx.x * blockDim.x + threadIdx.x;
    if (idx >= n_total) return;
    int bx = idx % NB;
    int by = (idx / NB) % NB;
    int n  = idx / (NB * NB);
    int r0 = by * BS - 1, c0 = bx * BS - 1;
    float m = -1e30f;
    for (int r = 0; r < 16; ++r) {
        int rr = r0 + r;
        if (rr < 0 || rr >= H) continue;
        const float* mrow = mask + ((long)n * H + rr) * H;
        int clo = (c0 < 0) ? 1 : 0;
        int chi = (c0 + 16 > H) ? 15 : 16;
        for (int c = clo; c < chi; ++c) m = fmaxf(m, mrow[c0 + c]);
    }
    g_active[idx] = (m > 0.5f) ? 1 : 0;
}

// ---------------- Kernel 2: HMMA block conv (fp16, 2-term) ----------------
__global__ void __launch_bounds__(NTHR, 2)
sbnet_mma_kernel(const float* __restrict__ x, const float* __restrict__ bias,
                 float* __restrict__ out) {
    extern __shared__ char smem[];
    const int tid  = threadIdx.x;
    const int wid  = tid >> 5;
    const int lane = tid & 31;
    const int bx = blockIdx.x % NB;
    const int by = blockIdx.x / NB;
    const int n  = blockIdx.y;

    if (!g_active[n * NB * NB + blockIdx.x]) {
        for (int i = tid; i < COUT * BS * BS; i += NTHR) {
            int co = i / (BS * BS);
            int rem = i % (BS * BS);
            int y = rem / BS, xx = rem % BS;
            out[((size_t)(n * COUT + co)) * HH + (size_t)(by * BS + y) * H + bx * BS + xx] = 0.0f;
        }
        return;
    }

    const uint32_t smem_base = smem_u32(smem);
    float* s_bias = (float*)(smem + OFF_BIAS);
    if (tid < COUT) s_bias[tid] = bias[tid];

    // ---- build transposed fp16 halo via fp32 scratch (aliases WBUF), 4 chunks ----
    const int r0 = by * BS - 1, c0 = bx * BS - 1;
    float* raw = (float*)(smem + OFF_RAW);
    for (int chunk = 0; chunk < 4; ++chunk) {
        __syncthreads();
        for (int i = tid; i < 16 * HAL * HAL; i += NTHR) {
            int ci = i / (HAL * HAL);
            int rem = i % (HAL * HAL);
            int y = rem / HAL, xx = rem % HAL;
            int rr = r0 + y, cc = c0 + xx;
            float v = 0.0f;
            if (rr >= 0 && rr < H && cc >= 0 && cc < H)
                v = x[((size_t)(n * CIN + chunk * 16 + ci)) * HH + (size_t)rr * H + cc];
            raw[ci * RAWCIN + y * RAW19 + xx] = v;
        }
        __syncthreads();
        for (int pos = tid; pos < HAL * HAL; pos += NTHR) {
            int y = pos / HAL, xx = pos % HAL;
            uint32_t hu[8];
            #pragma unroll
            for (int k = 0; k < 8; ++k) {
                float v0 = raw[(2 * k) * RAWCIN + y * RAW19 + xx];
                float v1 = raw[(2 * k + 1) * RAWCIN + y * RAW19 + xx];
                hu[k] = pack2(__float2half(v0), __float2half(v1));
            }
            int u0 = chunk * 2;
            int o0 = pos * 128 + (((u0    ) ^ (pos & 7)) << 4);
            int o1 = pos * 128 + (((u0 + 1) ^ (pos & 7)) << 4);
            *(uint4*)(smem + OFF_HALO + o0) = make_uint4(hu[0], hu[1], hu[2], hu[3]);
            *(uint4*)(smem + OFF_HALO + o1) = make_uint4(hu[4], hu[5], hu[6], hu[7]);
        }
    }
    __syncthreads();   // raw dead -> WBUF usable

    // stage W tap 0 into buffer 0
    {
        const uint4* src = (const uint4*)(g_wprep);
        uint4* dst = (uint4*)(smem + OFF_WBUF);
        #pragma unroll
        for (int j = 0; j < 4; ++j) dst[tid + j * 256] = src[tid + j * 256];
    }
    __syncthreads();

    // ---- main loop over 9 taps ----
    const int mg = wid >> 1;          // m-group 0..3
    const int ng = wid & 1;           // n-group 0..1
    const int cA = lane & 15;
    const int ksubA = lane >> 4;
    const int rB = lane & 7;
    const int msB = (lane >> 3) & 1;

    float acc[4][4][4];
    #pragma unroll
    for (int mt = 0; mt < 4; ++mt)
        #pragma unroll
        for (int nt = 0; nt < 4; ++nt)
            #pragma unroll
            for (int q = 0; q < 4; ++q) acc[mt][nt][q] = 0.0f;

    const uint32_t halo = smem_base + OFF_HALO;

    uint32_t coB[4];
    #pragma unroll
    for (int nt = 0; nt < 4; ++nt) coB[nt] = ng * 32 + nt * 8 + rB;

    #pragma unroll 1
    for (int tap = 0; tap < 9; ++tap) {
        const int dy = tap / 3, dx = tap - dy * 3;

        uint4 wpre[4];
        const bool pre = (tap + 1 < 9);
        if (pre) {
            const uint4* src = (const uint4*)(g_wprep + (tap + 1) * 16384);
            #pragma unroll
            for (int j = 0; j < 4; ++j) wpre[j] = src[tid + j * 256];
        }

        uint32_t posm[4];
        #pragma unroll
        for (int mt = 0; mt < 4; ++mt)
            posm[mt] = (mg * 4 + mt + dy) * HAL + cA + dx;

        const uint32_t wb = smem_base + OFF_WBUF + (tap & 1) * 16384;

        #pragma unroll
        for (int ks = 0; ks < 4; ++ks) {
            uint32_t ah[4][4], bh[4][2], bl[4][2];
            #pragma unroll
            for (int mt = 0; mt < 4; ++mt) {
                if (mg * 4 + mt < 14) {
                    uint32_t off = posm[mt] * 128 +
                        (((uint32_t)(ks * 2 + ksubA) ^ (posm[mt] & 7)) << 4);
                    ldsm_x4(ah[mt], halo + off);
                }
            }
            #pragma unroll
            for (int nt = 0; nt < 4; ++nt) {
                uint32_t off = coB[nt] * 128 +
                    (((uint32_t)(ks * 2 + msB) ^ (coB[nt] & 7)) << 4);
                ldsm_x2(bh[nt], wb + off);
                ldsm_x2(bl[nt], wb + 8192 + off);
            }
            #pragma unroll
            for (int mt = 0; mt < 4; ++mt) {
                if (mg * 4 + mt < 14) {
                    #pragma unroll
                    for (int nt = 0; nt < 4; ++nt) {
                        mma16816(acc[mt][nt], ah[mt], bh[nt]);
                        mma16816(acc[mt][nt], ah[mt], bl[nt]);
                    }
                }
            }
        }

        if (pre) {
            uint4* dst = (uint4*)(smem + OFF_WBUF + ((tap + 1) & 1) * 16384);
            #pragma unroll
            for (int j = 0; j < 4; ++j) dst[tid + j * 256] = wpre[j];
        }
        __syncthreads();
    }

    // ---- epilogue: accums -> smem transpose -> coalesced gmem ----
    float* epi = (float*)smem;     // [224][66], aliases halo + wbuf (dead)
    const int g  = lane >> 2;
    const int tg = lane & 3;
    #pragma unroll
    for (int mt = 0; mt < 4; ++mt) {
        int tile = mg * 4 + mt;
        if (tile < 14) {
            #pragma unroll
            for (int nt = 0; nt < 4; ++nt) {
                int p  = tile * 16 + g;
                int co = ng * 32 + nt * 8 + 2 * tg;
                *(float2*)&epi[p * 66 + co]       = make_float2(acc[mt][nt][0], acc[mt][nt][1]);
                *(float2*)&epi[(p + 8) * 66 + co] = make_float2(acc[mt][nt][2], acc[mt][nt][3]);
            }
        }
    }
    __syncthreads();

    for (int i = tid; i < COUT * BS * BS; i += NTHR) {
        int co = i / (BS * BS);
        int rem = i % (BS * BS);
        int y = rem / BS, xx = rem % BS;
        float val = epi[(y * 16 + xx) * 66 + co] + s_bias[co];
        out[((size_t)(n * COUT + co)) * HH + (size_t)(by * BS + y) * H + bx * BS + xx] = val;
    }
}

extern "C" void kernel_launch(void* const* d_in, const int* in_sizes, int n_in,
                              void* d_out, int out_size) {
    const float* x    = (const float*)d_in[0];
    const float* mask = (const float*)d_in[1];
    const float* w    = (const float*)d_in[2];
    const float* bias = (const float*)d_in[3];
    float* out = (float*)d_out;

    int N = in_sizes[0] / (CIN * H * H);   // 4
    int nblk = N * NB * NB;

    cudaFuncSetAttribute(sbnet_mma_kernel,
                         cudaFuncAttributeMaxDynamicSharedMemorySize, SMEM_TOTAL);

    sbnet_wprep_kernel<<<(9 * COUT * CIN + 255) / 256, 256>>>(w);
    sbnet_mask_kernel<<<(nblk + 255) / 256, 256>>>(mask, nblk);
    sbnet_mma_kernel<<<dim3(NB * NB, (unsigned)N), NTHR, SMEM_TOTAL>>>(x, bias, out);
}

// round 7
// speedup vs baseline: 4.1704x; 1.3689x over previous
#include <cuda_runtime.h>
#include <cuda_fp16.h>
#include <cstdint>

#define H    448
#define HH   (448*448)
#define CIN  64
#define COUT 64
#define NB   32
#define BS   14
#define HAL  18
#define NTHR 256

// ---- dynamic smem layout (bytes) ----
#define OFF_HALO    0                        // 18x18 pixels x 128B fp16 = 41472
#define OFF_RAW     41472                    // 16 x 18 x 19 f32 = 21888 (halo build scratch)
#define OFF_BIAS    63360                    // 64 f32
#define SMEM_TOTAL  63616
// epilogue aliases [0, 59136) = 224 x 66 f32  (halo+raw dead by then)

#define RAW19   19
#define RAWCIN  (HAL*RAW19)                  // 342 floats per cin

__device__ unsigned char g_active[4 * NB * NB];
// W in mma-fragment order: [tap][ng][nt][ks][lane] -> uint2 {b0, b1}
__device__ __align__(16) uint2 g_wfrag[9 * 2 * 4 * 4 * 32];

// ---------------- helpers ----------------
__device__ __forceinline__ uint32_t smem_u32(const void* p) {
    uint32_t a;
    asm("{ .reg .u64 t; cvta.to.shared.u64 t, %1; cvt.u32.u64 %0, t; }" : "=r"(a) : "l"(p));
    return a;
}
__device__ __forceinline__ void ldsm_x4(uint32_t* r, uint32_t addr) {
    asm volatile("ldmatrix.sync.aligned.m8n8.x4.shared.b16 {%0,%1,%2,%3}, [%4];"
        : "=r"(r[0]), "=r"(r[1]), "=r"(r[2]), "=r"(r[3]) : "r"(addr));
}
__device__ __forceinline__ void mma16816(float* d, const uint32_t* a, uint32_t b0, uint32_t b1) {
    asm volatile("mma.sync.aligned.m16n8k16.row.col.f32.f16.f16.f32 "
        "{%0,%1,%2,%3}, {%4,%5,%6,%7}, {%8,%9}, {%0,%1,%2,%3};"
        : "+f"(d[0]), "+f"(d[1]), "+f"(d[2]), "+f"(d[3])
        : "r"(a[0]), "r"(a[1]), "r"(a[2]), "r"(a[3]), "r"(b0), "r"(b1));
}
__device__ __forceinline__ uint32_t pack2(__half a, __half b) {
    return ((uint32_t)__half_as_ushort(b) << 16) | __half_as_ushort(a);
}
__device__ __forceinline__ void cp_async4(uint32_t dst, const float* src, bool pred) {
    asm volatile("cp.async.ca.shared.global [%0], [%1], 4, %2;"
        :: "r"(dst), "l"(src), "r"(pred ? 4u : 0u) : "memory");
}

// ---------------- Kernel 0: W fragment prep ----------------
__global__ void sbnet_wprep_kernel(const float* __restrict__ w) {
    int i = blockIdx.x * 256 + threadIdx.x;
    if (i >= 9 * 2 * 4 * 4 * 32) return;
    int tap  = i >> 10;
    int rem  = i & 1023;
    int ng   = rem >> 9;
    int nt   = (rem >> 7) & 3;
    int ks   = (rem >> 5) & 3;
    int lane = rem & 31;
    int co = ng * 32 + nt * 8 + (lane >> 2);
    int k0 = ks * 16 + (lane & 3) * 2;
    const float* wc = w + (size_t)co * CIN * 9 + tap;   // w[co][cin][tap]
    uint32_t b0 = pack2(__float2half(wc[(size_t)k0 * 9]),
                        __float2half(wc[(size_t)(k0 + 1) * 9]));
    uint32_t b1 = pack2(__float2half(wc[(size_t)(k0 + 8) * 9]),
                        __float2half(wc[(size_t)(k0 + 9) * 9]));
    g_wfrag[i] = make_uint2(b0, b1);
}

// ---------------- Kernel 1: block activity ----------------
__global__ void sbnet_mask_kernel(const float* __restrict__ mask, int n_total) {
    int idx = blockIdx.x * blockDim.x + threadIdx.x;
    if (idx >= n_total) return;
    int bx = idx % NB;
    int by = (idx / NB) % NB;
    int n  = idx / (NB * NB);
    int r0 = by * BS - 1, c0 = bx * BS - 1;
    float m = -1e30f;
    for (int r = 0; r < 16; ++r) {
        int rr = r0 + r;
        if (rr < 0 || rr >= H) continue;
        const float* mrow = mask + ((long)n * H + rr) * H;
        int clo = (c0 < 0) ? 1 : 0;
        int chi = (c0 + 16 > H) ? 15 : 16;
        for (int c = clo; c < chi; ++c) m = fmaxf(m, mrow[c0 + c]);
    }
    g_active[idx] = (m > 0.5f) ? 1 : 0;
}

// ---------------- Kernel 2: HMMA block conv (fp16 1-term, barrier-free mainloop) ----------------
__global__ void __launch_bounds__(NTHR, 2)
sbnet_mma_kernel(const float* __restrict__ x, const float* __restrict__ bias,
                 float* __restrict__ out) {
    extern __shared__ char smem[];
    const int tid  = threadIdx.x;
    const int wid  = tid >> 5;
    const int lane = tid & 31;
    const int bx = blockIdx.x % NB;
    const int by = blockIdx.x / NB;
    const int n  = blockIdx.y;

    if (!g_active[n * NB * NB + blockIdx.x]) {
        for (int i = tid; i < COUT * BS * BS; i += NTHR) {
            int co = i / (BS * BS);
            int rem = i % (BS * BS);
            int y = rem / BS, xx = rem % BS;
            out[((size_t)(n * COUT + co)) * HH + (size_t)(by * BS + y) * H + bx * BS + xx] = 0.0f;
        }
        return;
    }

    const uint32_t smem_base = smem_u32(smem);
    float* s_bias = (float*)(smem + OFF_BIAS);
    if (tid < COUT) s_bias[tid] = bias[tid];

    // ---- build transposed fp16 halo via fp32 scratch, 4 chunks of 16 cin ----
    const int r0 = by * BS - 1, c0 = bx * BS - 1;
    float* raw = (float*)(smem + OFF_RAW);
    const uint32_t raw_u = smem_base + OFF_RAW;
    for (int chunk = 0; chunk < 4; ++chunk) {
        __syncthreads();
        for (int i = tid; i < 16 * HAL * HAL; i += NTHR) {
            int ci = i / (HAL * HAL);
            int rem = i % (HAL * HAL);
            int y = rem / HAL, xx = rem % HAL;
            int rr = r0 + y, cc = c0 + xx;
            bool inb = (rr >= 0 && rr < H && cc >= 0 && cc < H);
            const float* src = x + ((size_t)(n * CIN + chunk * 16 + ci)) * HH
                                 + (size_t)(inb ? rr : 0) * H + (inb ? cc : 0);
            cp_async4(raw_u + (uint32_t)(ci * RAWCIN + y * RAW19 + xx) * 4, src, inb);
        }
        asm volatile("cp.async.commit_group;" ::: "memory");
        asm volatile("cp.async.wait_group 0;" ::: "memory");
        __syncthreads();
        for (int pos = tid; pos < HAL * HAL; pos += NTHR) {
            int y = pos / HAL, xx = pos % HAL;
            uint32_t hu[8];
            #pragma unroll
            for (int k = 0; k < 8; ++k) {
                float v0 = raw[(2 * k) * RAWCIN + y * RAW19 + xx];
                float v1 = raw[(2 * k + 1) * RAWCIN + y * RAW19 + xx];
                hu[k] = pack2(__float2half(v0), __float2half(v1));
            }
            int u0 = chunk * 2;
            int o0 = pos * 128 + (((u0    ) ^ (pos & 7)) << 4);
            int o1 = pos * 128 + (((u0 + 1) ^ (pos & 7)) << 4);
            *(uint4*)(smem + OFF_HALO + o0) = make_uint4(hu[0], hu[1], hu[2], hu[3]);
            *(uint4*)(smem + OFF_HALO + o1) = make_uint4(hu[4], hu[5], hu[6], hu[7]);
        }
    }
    __syncthreads();

    // ---- main loop over 9 taps: NO barriers, W via fragment LDGs ----
    const int mg = wid >> 1;          // m-group 0..3
    const int ng = wid & 1;           // n-group 0..1
    const int cA = lane & 15;
    const int ksubA = lane >> 4;
    const int ntiles = (mg == 3) ? 2 : 4;   // mg3 rows 14,15 are junk

    float acc[4][4][4];
    #pragma unroll
    for (int mt = 0; mt < 4; ++mt)
        #pragma unroll
        for (int nt = 0; nt < 4; ++nt)
            #pragma unroll
            for (int q = 0; q < 4; ++q) acc[mt][nt][q] = 0.0f;

    const uint32_t halo = smem_base + OFF_HALO;
    const uint2* wf = g_wfrag + ng * 512 + lane;   // + tap*1024 + nt*128 + ks*32

    #pragma unroll 1
    for (int tap = 0; tap < 9; ++tap) {
        const int dy = tap / 3, dx = tap - dy * 3;
        uint32_t posm[4];
        #pragma unroll
        for (int mt = 0; mt < 4; ++mt)
            posm[mt] = (mg * 4 + mt + dy) * HAL + cA + dx;
        const uint2* wt = wf + tap * 1024;

        #pragma unroll
        for (int ks = 0; ks < 4; ++ks) {
            uint32_t ah[4][4];
            uint2 b[4];
            #pragma unroll
            for (int mt = 0; mt < 4; ++mt) {
                if (mt < ntiles) {
                    uint32_t off = posm[mt] * 128 +
                        (((uint32_t)(ks * 2 + ksubA) ^ (posm[mt] & 7)) << 4);
                    ldsm_x4(ah[mt], halo + off);
                }
            }
            #pragma unroll
            for (int nt = 0; nt < 4; ++nt)
                b[nt] = __ldg(wt + nt * 128 + ks * 32);
            #pragma unroll
            for (int mt = 0; mt < 4; ++mt) {
                if (mt < ntiles) {
                    #pragma unroll
                    for (int nt = 0; nt < 4; ++nt)
                        mma16816(acc[mt][nt], ah[mt], b[nt].x, b[nt].y);
                }
            }
        }
    }

    // ---- epilogue: accums -> smem transpose -> coalesced gmem ----
    __syncthreads();               // halo/raw dead -> epi aliasing safe
    float* epi = (float*)smem;     // [224][66]
    const int g  = lane >> 2;
    const int tg = lane & 3;
    #pragma unroll
    for (int mt = 0; mt < 4; ++mt) {
        int tile = mg * 4 + mt;
        if (tile < 14) {
            #pragma unroll
            for (int nt = 0; nt < 4; ++nt) {
                int p  = tile * 16 + g;
                int co = ng * 32 + nt * 8 + 2 * tg;
                *(float2*)&epi[p * 66 + co]       = make_float2(acc[mt][nt][0], acc[mt][nt][1]);
                *(float2*)&epi[(p + 8) * 66 + co] = make_float2(acc[mt][nt][2], acc[mt][nt][3]);
            }
        }
    }
    __syncthreads();

    for (int i = tid; i < COUT * BS * BS; i += NTHR) {
        int co = i / (BS * BS);
        int rem = i % (BS * BS);
        int y = rem / BS, xx = rem % BS;
        float val = epi[(y * 16 + xx) * 66 + co] + s_bias[co];
        out[((size_t)(n * COUT + co)) * HH + (size_t)(by * BS + y) * H + bx * BS + xx] = val;
    }
}

extern "C" void kernel_launch(void* const* d_in, const int* in_sizes, int n_in,
                              void* d_out, int out_size) {
    const float* x    = (const float*)d_in[0];
    const float* mask = (const float*)d_in[1];
    const float* w    = (const float*)d_in[2];
    const float* bias = (const float*)d_in[3];
    float* out = (float*)d_out;

    int N = in_sizes[0] / (CIN * H * H);   // 4
    int nblk = N * NB * NB;

    cudaFuncSetAttribute(sbnet_mma_kernel,
                         cudaFuncAttributeMaxDynamicSharedMemorySize, SMEM_TOTAL);

    sbnet_wprep_kernel<<<(9 * 2 * 4 * 4 * 32 + 255) / 256, 256>>>(w);
    sbnet_mask_kernel<<<(nblk + 255) / 256, 256>>>(mask, nblk);
    sbnet_mma_kernel<<<dim3(NB * NB, (unsigned)N), NTHR, SMEM_TOTAL>>>(x, bias, out);
}

// round 8
// speedup vs baseline: 4.7814x; 1.1465x over previous
#include <cuda_runtime.h>
#include <cuda_fp16.h>
#include <cstdint>

#define H    448
#define HH   (448*448)
#define CIN  64
#define COUT 64
#define NB   32
#define BS   14
#define HAL  18
#define NTHR 256

// ---- dynamic smem layout (bytes) ----
#define OFF_HALO    0                        // 18x18 pixels x 128B fp16 = 41472
#define OFF_RAW     41472                    // 16 cin x 18 rows x 24 f32 = 27648
#define OFF_BIAS    69120                    // 64 f32
#define SMEM_TOTAL  69376
// epilogue aliases [0, 59136) = 224 x 66 f32 (halo+raw dead by then)

#define RAW24   24
#define RAWC    (HAL*RAW24)                  // 432 floats per cin

__device__ unsigned char g_active[4 * NB * NB];
// W in mma-fragment order: [tap][nt'][ks][lane] -> uint2 {b0, b1}, nt' = 0..7
__device__ __align__(16) uint2 g_wfrag[9 * 8 * 4 * 32];

// ---------------- helpers ----------------
__device__ __forceinline__ uint32_t smem_u32(const void* p) {
    uint32_t a;
    asm("{ .reg .u64 t; cvta.to.shared.u64 t, %1; cvt.u32.u64 %0, t; }" : "=r"(a) : "l"(p));
    return a;
}
__device__ __forceinline__ void ldsm_x4(uint32_t* r, uint32_t addr) {
    asm volatile("ldmatrix.sync.aligned.m8n8.x4.shared.b16 {%0,%1,%2,%3}, [%4];"
        : "=r"(r[0]), "=r"(r[1]), "=r"(r[2]), "=r"(r[3]) : "r"(addr));
}
__device__ __forceinline__ void mma16816(float* d, const uint32_t* a, uint32_t b0, uint32_t b1) {
    asm volatile("mma.sync.aligned.m16n8k16.row.col.f32.f16.f16.f32 "
        "{%0,%1,%2,%3}, {%4,%5,%6,%7}, {%8,%9}, {%0,%1,%2,%3};"
        : "+f"(d[0]), "+f"(d[1]), "+f"(d[2]), "+f"(d[3])
        : "r"(a[0]), "r"(a[1]), "r"(a[2]), "r"(a[3]), "r"(b0), "r"(b1));
}
__device__ __forceinline__ uint32_t pack2(__half a, __half b) {
    return ((uint32_t)__half_as_ushort(b) << 16) | __half_as_ushort(a);
}
__device__ __forceinline__ void cp_async16(uint32_t dst, const float* src, bool pred) {
    asm volatile("cp.async.cg.shared.global [%0], [%1], 16, %2;"
        :: "r"(dst), "l"(src), "r"(pred ? 16u : 0u) : "memory");
}

// ---------------- Kernel 0: W fragment prep (layout linear in nt') ----------------
__global__ void sbnet_wprep_kernel(const float* __restrict__ w) {
    int i = blockIdx.x * 256 + threadIdx.x;
    if (i >= 9 * 8 * 4 * 32) return;
    int tap  = i >> 10;
    int rem  = i & 1023;
    int nt   = rem >> 7;          // 0..7
    int ks   = (rem >> 5) & 3;
    int lane = rem & 31;
    int co = nt * 8 + (lane >> 2);
    int k0 = ks * 16 + (lane & 3) * 2;
    const float* wc = w + (size_t)co * CIN * 9 + tap;   // w[co][cin][tap]
    uint32_t b0 = pack2(__float2half(wc[(size_t)k0 * 9]),
                        __float2half(wc[(size_t)(k0 + 1) * 9]));
    uint32_t b1 = pack2(__float2half(wc[(size_t)(k0 + 8) * 9]),
                        __float2half(wc[(size_t)(k0 + 9) * 9]));
    g_wfrag[i] = make_uint2(b0, b1);
}

// ---------------- Kernel 1: block activity ----------------
__global__ void sbnet_mask_kernel(const float* __restrict__ mask, int n_total) {
    int idx = blockIdx.x * blockDim.x + threadIdx.x;
    if (idx >= n_total) return;
    int bx = idx % NB;
    int by = (idx / NB) % NB;
    int n  = idx / (NB * NB);
    int r0 = by * BS - 1, c0 = bx * BS - 1;
    float m = -1e30f;
    for (int r = 0; r < 16; ++r) {
        int rr = r0 + r;
        if (rr < 0 || rr >= H) continue;
        const float* mrow = mask + ((long)n * H + rr) * H;
        int clo = (c0 < 0) ? 1 : 0;
        int chi = (c0 + 16 > H) ? 15 : 16;
        for (int c = clo; c < chi; ++c) m = fmaxf(m, mrow[c0 + c]);
    }
    g_active[idx] = (m > 0.5f) ? 1 : 0;
}

// ---------------- Kernel 2: HMMA block conv ----------------
__global__ void __launch_bounds__(NTHR, 2)
sbnet_mma_kernel(const float* __restrict__ x, const float* __restrict__ bias,
                 float* __restrict__ out) {
    extern __shared__ char smem[];
    const int tid  = threadIdx.x;
    const int wid  = tid >> 5;
    const int lane = tid & 31;
    const int bx = blockIdx.x % NB;
    const int by = blockIdx.x / NB;
    const int n  = blockIdx.y;

    if (!g_active[n * NB * NB + blockIdx.x]) {
        for (int i = tid; i < COUT * BS * BS; i += NTHR) {
            int co = i / (BS * BS);
            int rem = i % (BS * BS);
            int y = rem / BS, xx = rem % BS;
            out[((size_t)(n * COUT + co)) * HH + (size_t)(by * BS + y) * H + bx * BS + xx] = 0.0f;
        }
        return;
    }

    const uint32_t smem_base = smem_u32(smem);
    float* s_bias = (float*)(smem + OFF_BIAS);
    if (tid < COUT) s_bias[tid] = bias[tid];

    // ---- build transposed fp16 halo via aligned float4 cp.async staging ----
    const int r0 = by * BS - 1, c0 = bx * BS - 1;
    const int cb0 = (c0 < 0) ? 0 : (c0 & ~3);   // aligned fetch base
    const int coff = c0 - cb0;                  // -1..3; raw col idx = coff + xx
    float* raw = (float*)(smem + OFF_RAW);
    const uint32_t raw_u = smem_base + OFF_RAW;

    for (int chunk = 0; chunk < 4; ++chunk) {
        __syncthreads();
        // 16 cin x 18 rows x 6 float4 = 1728 cp.async.16
        for (int i = tid; i < 16 * HAL * 6; i += NTHR) {
            int j  = i % 6;
            int y  = (i / 6) % HAL;
            int ci = i / (6 * HAL);
            int rr = r0 + y;
            int s  = cb0 + j * 4;
            bool inb = (rr >= 0 && rr < H && s < H);
            const float* src = x + ((size_t)(n * CIN + chunk * 16 + ci)) * HH
                                 + (size_t)(inb ? rr : 0) * H + (inb ? s : 0);
            cp_async16(raw_u + (uint32_t)(ci * RAWC + y * RAW24 + j * 4) * 4, src, inb);
        }
        asm volatile("cp.async.commit_group;" ::: "memory");
        asm volatile("cp.async.wait_group 0;" ::: "memory");
        __syncthreads();
        for (int pos = tid; pos < HAL * HAL; pos += NTHR) {
            int y = pos / HAL, xx = pos % HAL;
            int cc = c0 + xx;
            bool cin_ok = (cc >= 0 && cc < H);
            int idx = y * RAW24 + coff + xx;
            uint32_t hu[8];
            #pragma unroll
            for (int k = 0; k < 8; ++k) {
                float v0 = cin_ok ? raw[(2 * k) * RAWC + idx] : 0.0f;
                float v1 = cin_ok ? raw[(2 * k + 1) * RAWC + idx] : 0.0f;
                hu[k] = pack2(__float2half(v0), __float2half(v1));
            }
            int u0 = chunk * 2;
            int o0 = pos * 128 + (((u0    ) ^ (pos & 7)) << 4);
            int o1 = pos * 128 + (((u0 + 1) ^ (pos & 7)) << 4);
            *(uint4*)(smem + OFF_HALO + o0) = make_uint4(hu[0], hu[1], hu[2], hu[3]);
            *(uint4*)(smem + OFF_HALO + o1) = make_uint4(hu[4], hu[5], hu[6], hu[7]);
        }
    }
    __syncthreads();

    // ---- main loop: warp = 2 m-tiles x all 8 n-tiles; no A duplication ----
    const int mt0 = wid * 2;                 // tiles mt0, mt0+1; warp7 -> junk rows
    const bool act = (mt0 < 14);
    const int cA = lane & 15;
    const int ksubA = lane >> 4;

    float acc[2][8][4];
    #pragma unroll
    for (int mt = 0; mt < 2; ++mt)
        #pragma unroll
        for (int nt = 0; nt < 8; ++nt)
            #pragma unroll
            for (int q = 0; q < 4; ++q) acc[mt][nt][q] = 0.0f;

    const uint32_t halo = smem_base + OFF_HALO;
    const uint2* wf = g_wfrag + lane;        // + tap*1024 + nt*128 + ks*32

    if (act) {
        #pragma unroll 1
        for (int tap = 0; tap < 9; ++tap) {
            const int dy = tap / 3, dx = tap - dy * 3;
            uint32_t posm[2];
            #pragma unroll
            for (int mt = 0; mt < 2; ++mt)
                posm[mt] = (mt0 + mt + dy) * HAL + cA + dx;
            const uint2* wt = wf + tap * 1024;

            #pragma unroll
            for (int ks = 0; ks < 4; ++ks) {
                uint32_t ah[2][4];
                uint2 b[8];
                #pragma unroll
                for (int mt = 0; mt < 2; ++mt) {
                    uint32_t off = posm[mt] * 128 +
                        (((uint32_t)(ks * 2 + ksubA) ^ (posm[mt] & 7)) << 4);
                    ldsm_x4(ah[mt], halo + off);
                }
                #pragma unroll
                for (int nt = 0; nt < 8; ++nt)
                    b[nt] = __ldg(wt + nt * 128 + ks * 32);
                #pragma unroll
                for (int mt = 0; mt < 2; ++mt)
                    #pragma unroll
                    for (int nt = 0; nt < 8; ++nt)
                        mma16816(acc[mt][nt], ah[mt], b[nt].x, b[nt].y);
            }
        }
    }

    // ---- epilogue: accums -> smem transpose -> coalesced gmem ----
    __syncthreads();               // halo/raw dead -> epi aliasing safe
    float* epi = (float*)smem;     // [224][66]
    const int g  = lane >> 2;
    const int tg = lane & 3;
    if (act) {
        #pragma unroll
        for (int mt = 0; mt < 2; ++mt) {
            int tile = mt0 + mt;
            #pragma unroll
            for (int nt = 0; nt < 8; ++nt) {
                int p  = tile * 16 + g;
                int co = nt * 8 + 2 * tg;
                *(float2*)&epi[p * 66 + co]       = make_float2(acc[mt][nt][0], acc[mt][nt][1]);
                *(float2*)&epi[(p + 8) * 66 + co] = make_float2(acc[mt][nt][2], acc[mt][nt][3]);
            }
        }
    }
    __syncthreads();

    for (int i = tid; i < COUT * BS * BS; i += NTHR) {
        int co = i / (BS * BS);
        int rem = i % (BS * BS);
        int y = rem / BS, xx = rem % BS;
        float val = epi[(y * 16 + xx) * 66 + co] + s_bias[co];
        out[((size_t)(n * COUT + co)) * HH + (size_t)(by * BS + y) * H + bx * BS + xx] = val;
    }
}

extern "C" void kernel_launch(void* const* d_in, const int* in_sizes, int n_in,
                              void* d_out, int out_size) {
    const float* x    = (const float*)d_in[0];
    const float* mask = (const float*)d_in[1];
    const float* w    = (const float*)d_in[2];
    const float* bias = (const float*)d_in[3];
    float* out = (float*)d_out;

    int N = in_sizes[0] / (CIN * H * H);   // 4
    int nblk = N * NB * NB;

    cudaFuncSetAttribute(sbnet_mma_kernel,
                         cudaFuncAttributeMaxDynamicSharedMemorySize, SMEM_TOTAL);

    sbnet_wprep_kernel<<<(9 * 8 * 4 * 32 + 255) / 256, 256>>>(w);
    sbnet_mask_kernel<<<(nblk + 255) / 256, 256>>>(mask, nblk);
    sbnet_mma_kernel<<<dim3(NB * NB, (unsigned)N), NTHR, SMEM_TOTAL>>>(x, bias, out);
}

// round 9
// speedup vs baseline: 4.8792x; 1.0205x over previous
#include <cuda_runtime.h>
#include <cuda_fp16.h>
#include <cstdint>

#define H    448
#define HH   (448*448)
#define CIN  64
#define COUT 64
#define NB   32
#define BS   14
#define HAL  18
#define NTHR 256

// ---- dynamic smem layout (bytes) ----
// per-chunk halo: 324 pos x 32B (16 cin fp16), double buffered
#define HC_BYTES    (HAL*HAL*32)             // 10368
#define OFF_HC0     0
#define OFF_HC1     10368
#define OFF_RAW0    20736                    // 16 cin x 18 rows x 24 f32 = 27648
#define OFF_RAW1    48384
#define OFF_BIAS    76032                    // 64 f32
#define SMEM_TOTAL  76288
// epilogue aliases [0, 59136) = 224 x 66 f32 (halo/raw dead by then)

#define RAW24   24
#define RAWC    (HAL*RAW24)                  // 432 floats per cin

__device__ unsigned char g_active[4 * NB * NB];
// W in mma-fragment order: [tap][nt][chunk][lane] -> uint2 {b0, b1}
__device__ __align__(16) uint2 g_wfrag[9 * 8 * 4 * 32];

// ---------------- helpers ----------------
__device__ __forceinline__ uint32_t smem_u32(const void* p) {
    uint32_t a;
    asm("{ .reg .u64 t; cvta.to.shared.u64 t, %1; cvt.u32.u64 %0, t; }" : "=r"(a) : "l"(p));
    return a;
}
__device__ __forceinline__ void ldsm_x4(uint32_t* r, uint32_t addr) {
    asm volatile("ldmatrix.sync.aligned.m8n8.x4.shared.b16 {%0,%1,%2,%3}, [%4];"
        : "=r"(r[0]), "=r"(r[1]), "=r"(r[2]), "=r"(r[3]) : "r"(addr));
}
__device__ __forceinline__ void mma16816(float* d, const uint32_t* a, uint32_t b0, uint32_t b1) {
    asm volatile("mma.sync.aligned.m16n8k16.row.col.f32.f16.f16.f32 "
        "{%0,%1,%2,%3}, {%4,%5,%6,%7}, {%8,%9}, {%0,%1,%2,%3};"
        : "+f"(d[0]), "+f"(d[1]), "+f"(d[2]), "+f"(d[3])
        : "r"(a[0]), "r"(a[1]), "r"(a[2]), "r"(a[3]), "r"(b0), "r"(b1));
}
__device__ __forceinline__ uint32_t pack2(__half a, __half b) {
    return ((uint32_t)__half_as_ushort(b) << 16) | __half_as_ushort(a);
}
__device__ __forceinline__ void cp_async16(uint32_t dst, const float* src, bool pred) {
    asm volatile("cp.async.cg.shared.global [%0], [%1], 16, %2;"
        :: "r"(dst), "l"(src), "r"(pred ? 16u : 0u) : "memory");
}

// ---------------- Kernel 0: W fragment prep ----------------
__global__ void sbnet_wprep_kernel(const float* __restrict__ w) {
    int i = blockIdx.x * 256 + threadIdx.x;
    if (i >= 9 * 8 * 4 * 32) return;
    int tap  = i >> 10;
    int rem  = i & 1023;
    int nt   = rem >> 7;          // 0..7
    int ks   = (rem >> 5) & 3;    // cin chunk
    int lane = rem & 31;
    int co = nt * 8 + (lane >> 2);
    int k0 = ks * 16 + (lane & 3) * 2;
    const float* wc = w + (size_t)co * CIN * 9 + tap;   // w[co][cin][tap]
    uint32_t b0 = pack2(__float2half(wc[(size_t)k0 * 9]),
                        __float2half(wc[(size_t)(k0 + 1) * 9]));
    uint32_t b1 = pack2(__float2half(wc[(size_t)(k0 + 8) * 9]),
                        __float2half(wc[(size_t)(k0 + 9) * 9]));
    g_wfrag[i] = make_uint2(b0, b1);
}

// ---------------- Kernel 1: block activity ----------------
__global__ void sbnet_mask_kernel(const float* __restrict__ mask, int n_total) {
    int idx = blockIdx.x * blockDim.x + threadIdx.x;
    if (idx >= n_total) return;
    int bx = idx % NB;
    int by = (idx / NB) % NB;
    int n  = idx / (NB * NB);
    int r0 = by * BS - 1, c0 = bx * BS - 1;
    float m = -1e30f;
    for (int r = 0; r < 16; ++r) {
        int rr = r0 + r;
        if (rr < 0 || rr >= H) continue;
        const float* mrow = mask + ((long)n * H + rr) * H;
        int clo = (c0 < 0) ? 1 : 0;
        int chi = (c0 + 16 > H) ? 15 : 16;
        for (int c = clo; c < chi; ++c) m = fmaxf(m, mrow[c0 + c]);
    }
    g_active[idx] = (m > 0.5f) ? 1 : 0;
}

// ---------------- Kernel 2: HMMA block conv, chunk-pipelined ----------------
__global__ void __launch_bounds__(NTHR, 2)
sbnet_mma_kernel(const float* __restrict__ x, const float* __restrict__ bias,
                 float* __restrict__ out) {
    extern __shared__ char smem[];
    const int tid  = threadIdx.x;
    const int wid  = tid >> 5;
    const int lane = tid & 31;
    const int bx = blockIdx.x % NB;
    const int by = blockIdx.x / NB;
    const int n  = blockIdx.y;

    if (!g_active[n * NB * NB + blockIdx.x]) {
        for (int i = tid; i < COUT * BS * BS; i += NTHR) {
            int co = i / (BS * BS);
            int rem = i % (BS * BS);
            int y = rem / BS, xx = rem % BS;
            out[((size_t)(n * COUT + co)) * HH + (size_t)(by * BS + y) * H + bx * BS + xx] = 0.0f;
        }
        return;
    }

    const uint32_t smem_base = smem_u32(smem);
    float* s_bias = (float*)(smem + OFF_BIAS);
    if (tid < COUT) s_bias[tid] = bias[tid];

    const int r0 = by * BS - 1, c0 = bx * BS - 1;
    const int cb0 = (c0 < 0) ? 0 : (c0 & ~3);   // aligned fetch base
    const int coff = c0 - cb0;                  // raw col idx = coff + xx

    // issue chunk c's raw load into raw[buf]
    auto issue_load = [&](int chunk, int buf) {
        uint32_t rb = smem_base + (buf ? OFF_RAW1 : OFF_RAW0);
        for (int i = tid; i < 16 * HAL * 6; i += NTHR) {
            int j  = i % 6;
            int y  = (i / 6) % HAL;
            int ci = i / (6 * HAL);
            int rr = r0 + y;
            int s  = cb0 + j * 4;
            bool inb = (rr >= 0 && rr < H && s < H);
            const float* src = x + ((size_t)(n * CIN + chunk * 16 + ci)) * HH
                                 + (size_t)(inb ? rr : 0) * H + (inb ? s : 0);
            cp_async16(rb + (uint32_t)(ci * RAWC + y * RAW24 + j * 4) * 4, src, inb);
        }
        asm volatile("cp.async.commit_group;" ::: "memory");
    };

    // convert raw[buf] -> chunk halo hc[buf] (16 cin fp16, swizzled 32B rows)
    auto convert = [&](int buf) {
        const float* raw = (const float*)(smem + (buf ? OFF_RAW1 : OFF_RAW0));
        char* hc = smem + (buf ? OFF_HC1 : OFF_HC0);
        for (int pos = tid; pos < HAL * HAL; pos += NTHR) {
            int y = pos / HAL, xx = pos % HAL;
            int cc = c0 + xx;
            bool cin_ok = (cc >= 0 && cc < H);
            int idx = y * RAW24 + coff + xx;
            uint32_t hu[8];
            #pragma unroll
            for (int k = 0; k < 8; ++k) {
                float v0 = cin_ok ? raw[(2 * k) * RAWC + idx] : 0.0f;
                float v1 = cin_ok ? raw[(2 * k + 1) * RAWC + idx] : 0.0f;
                hu[k] = pack2(__float2half(v0), __float2half(v1));
            }
            int sw = (pos >> 2) & 1;
            *(uint4*)(hc + pos * 32 + ((0 ^ sw) << 4)) = make_uint4(hu[0], hu[1], hu[2], hu[3]);
            *(uint4*)(hc + pos * 32 + ((1 ^ sw) << 4)) = make_uint4(hu[4], hu[5], hu[6], hu[7]);
        }
    };

    const int mt0 = wid * 2;                 // m-tiles (output rows) mt0, mt0+1
    const bool act = (mt0 < 14);
    const int cA = lane & 15;
    const int ksubA = lane >> 4;

    float acc[2][8][4];
    #pragma unroll
    for (int mt = 0; mt < 2; ++mt)
        #pragma unroll
        for (int nt = 0; nt < 8; ++nt)
            #pragma unroll
            for (int q = 0; q < 4; ++q) acc[mt][nt][q] = 0.0f;

    const uint2* wf = g_wfrag + lane;        // + tap*1024 + nt*128 + chunk*32

    // ---- prologue: load + convert chunk 0 ----
    issue_load(0, 0);
    asm volatile("cp.async.wait_group 0;" ::: "memory");
    __syncthreads();
    convert(0);
    __syncthreads();

    // ---- pipelined chunk loop ----
    #pragma unroll 1
    for (int c = 0; c < 4; ++c) {
        const int buf = c & 1;
        if (c < 3) issue_load(c + 1, buf ^ 1);

        if (act) {
            const uint32_t hc = smem_base + (buf ? OFF_HC1 : OFF_HC0);
            #pragma unroll
            for (int tap = 0; tap < 9; ++tap) {
                const int dy = tap / 3, dx = tap - dy * 3;
                uint32_t ah[2][4];
                uint2 b[8];
                #pragma unroll
                for (int mt = 0; mt < 2; ++mt) {
                    uint32_t pm = (mt0 + mt + dy) * HAL + cA + dx;
                    uint32_t off = pm * 32 + (((uint32_t)ksubA ^ ((pm >> 2) & 1)) << 4);
                    ldsm_x4(ah[mt], hc + off);
                }
                const uint2* wt = wf + tap * 1024 + c * 32;
                #pragma unroll
                for (int nt = 0; nt < 8; ++nt)
                    b[nt] = __ldg(wt + nt * 128);
                #pragma unroll
                for (int mt = 0; mt < 2; ++mt)
                    #pragma unroll
                    for (int nt = 0; nt < 8; ++nt)
                        mma16816(acc[mt][nt], ah[mt], b[nt].x, b[nt].y);
            }
        }

        if (c < 3) {
            asm volatile("cp.async.wait_group 0;" ::: "memory");
            __syncthreads();
            convert(buf ^ 1);
            __syncthreads();
        }
    }

    // ---- epilogue: accums -> smem transpose -> coalesced gmem ----
    __syncthreads();               // halo/raw dead -> epi aliasing safe
    float* epi = (float*)smem;     // [224][66]
    const int g  = lane >> 2;
    const int tg = lane & 3;
    if (act) {
        #pragma unroll
        for (int mt = 0; mt < 2; ++mt) {
            int tile = mt0 + mt;
            #pragma unroll
            for (int nt = 0; nt < 8; ++nt) {
                int p  = tile * 16 + g;
                int co = nt * 8 + 2 * tg;
                *(float2*)&epi[p * 66 + co]       = make_float2(acc[mt][nt][0], acc[mt][nt][1]);
                *(float2*)&epi[(p + 8) * 66 + co] = make_float2(acc[mt][nt][2], acc[mt][nt][3]);
            }
        }
    }
    __syncthreads();

    for (int i = tid; i < COUT * BS * BS; i += NTHR) {
        int co = i / (BS * BS);
        int rem = i % (BS * BS);
        int y = rem / BS, xx = rem % BS;
        float val = epi[(y * 16 + xx) * 66 + co] + s_bias[co];
        out[((size_t)(n * COUT + co)) * HH + (size_t)(by * BS + y) * H + bx * BS + xx] = val;
    }
}

extern "C" void kernel_launch(void* const* d_in, const int* in_sizes, int n_in,
                              void* d_out, int out_size) {
    const float* x    = (const float*)d_in[0];
    const float* mask = (const float*)d_in[1];
    const float* w    = (const float*)d_in[2];
    const float* bias = (const float*)d_in[3];
    float* out = (float*)d_out;

    int N = in_sizes[0] / (CIN * H * H);   // 4
    int nblk = N * NB * NB;

    cudaFuncSetAttribute(sbnet_mma_kernel,
                         cudaFuncAttributeMaxDynamicSharedMemorySize, SMEM_TOTAL);

    sbnet_wprep_kernel<<<(9 * 8 * 4 * 32 + 255) / 256, 256>>>(w);
    sbnet_mask_kernel<<<(nblk + 255) / 256, 256>>>(mask, nblk);
    sbnet_mma_kernel<<<dim3(NB * NB, (unsigned)N), NTHR, SMEM_TOTAL>>>(x, bias, out);
}